// round 13
// baseline (speedup 1.0000x reference)
#include <cuda_runtime.h>
#include <math_constants.h>

#define NP 128           // particles
#define NB 512           // batch
#define NH 512           // hidden
#define PB (NP*NB)       // 65536
#define CQ 0.00390625f   // (1-alpha)/P = 0.5/128
#define BAND 0.004f      // near-tie fallback band (rel); fast-key err <= ~6e-5

// threefry key from jax.random.key(42): (k0=0, k1=42)
#define KS0 0u
#define KS1 42u
#define KS2 (KS0 ^ KS1 ^ 0x1BD11BDAu)

__device__ float d_lw[PB];    // d_lw[b*128 + s]
__device__ int   d_cnt[NB];   // warp-arrival counters (zero-init; self-reset)

// opaque multiply-by-one -> IMAD on the fma pipe, bit-exact
__device__ __forceinline__ unsigned imad1(unsigned a, unsigned one, unsigned c) {
    unsigned d;
    asm("mad.lo.u32 %0, %1, %2, %3;" : "=r"(d) : "r"(a), "r"(one), "r"(c));
    return d;
}

// fast-path threefry round: add on fma pipe, rot+xor on alu pipe
#define TFR(r) { x0 = imad1(x0, one, x1); x1 = __funnelshift_l(x1, x1, (r)); x1 ^= x0; }
// exact fallback-path round (original form; same bits either way)
#define TFROUND(r) { x0 += x1; x1 = __funnelshift_l(x1, x1, (r)); x1 ^= x0; }

// jax partitionable threefry, pipe-balanced (bit-identical)
__device__ __forceinline__ unsigned tf_bits_bal(unsigned i, unsigned one) {
    unsigned x0 = KS0;
    unsigned x1 = i + KS1;
    TFR(13) TFR(15) TFR(26) TFR(6)
    x0 = imad1(x0, one, KS1); x1 = imad1(x1, one, KS2 + 1u);
    TFR(17) TFR(29) TFR(16) TFR(24)
    x0 = imad1(x0, one, KS2); x1 = imad1(x1, one, KS0 + 2u);
    TFR(13) TFR(15) TFR(26) TFR(6)
    x0 = imad1(x0, one, KS0); x1 = imad1(x1, one, KS1 + 3u);
    TFR(17) TFR(29) TFR(16) TFR(24)
    x0 = imad1(x0, one, KS1); x1 = imad1(x1, one, KS2 + 4u);
    TFR(13) TFR(15) TFR(26) TFR(6)
    x0 = imad1(x0, one, KS2); x1 = imad1(x1, one, KS0 + 5u);
    return x0 ^ x1;
}

// exact-path threefry (identical bits; used in fallback)
__device__ __forceinline__ unsigned tf_bits(unsigned i) {
    unsigned x0 = KS0;
    unsigned x1 = i + KS1;
    TFROUND(13) TFROUND(15) TFROUND(26) TFROUND(6)
    x0 += KS1; x1 += KS2 + 1u;
    TFROUND(17) TFROUND(29) TFROUND(16) TFROUND(24)
    x0 += KS2; x1 += KS0 + 2u;
    TFROUND(13) TFROUND(15) TFROUND(26) TFROUND(6)
    x0 += KS0; x1 += KS1 + 3u;
    TFROUND(17) TFROUND(29) TFROUND(16) TFROUND(24)
    x0 += KS1; x1 += KS2 + 4u;
    TFROUND(13) TFROUND(15) TFROUND(26) TFROUND(6)
    x0 += KS2; x1 += KS0 + 5u;
    return x0 ^ x1;
}

__device__ __forceinline__ float uniform_from_bits(unsigned bits) {  // fallback path
    unsigned fb = (bits >> 9) | 0x3f800000u;
    float f = __uint_as_float(fb) - 1.0f;
    return fmaxf(f, 1.17549435082228751e-38f);
}

__device__ __forceinline__ float gumbel_precise(float u) {           // fallback path
    return -logf(-logf(u));
}

// fast path: u via IMAD.HI (fma pipe), key = lg2(u)*mq (positive, argmin).
// near-1 branchless poly fix (err <= ~5e-6 rel, band covers).
__device__ __forceinline__ unsigned fast_key_packed(unsigned bits, float mq, int p) {
    unsigned fb = __umulhi(bits, 0x800000u) + 0x3f800000u;  // == (bits>>9)|0x3f800000
    float u = __uint_as_float(fb) - 1.0f;                   // u==0 -> key=+inf (never wins)
    float lgm = __log2f(u);
    float x = u - 1.0f;
    float lgp = x * fmaf(x, -0.7213475204444817f, 1.4426950408889634f);
    float lg = (u > 0.996f) ? lgp : lgm;
    float key = lg * mq;
    return (__float_as_uint(key) & 0xFFFFFF80u) | (unsigned)p;
}

// Single kernel: block (b, g) g in [0,4) owns draws s = g*32 .. g*32+31 of
// column b. Each warp processes 2 draw-pairs sequentially; warps retire
// independently (no epilogue barrier). The 32nd arriving warp of a column
// computes that column's logsumexp.
__global__ __launch_bounds__(256, 7) void sample_gather_kernel(
        const float* __restrict__ particles,
        const float* __restrict__ prob,
        float* __restrict__ out_particles,
        float* __restrict__ out_prob,
        unsigned one) {
    __shared__ float sh_lt[NP];    // log(resamp_p)   (exact path)
    __shared__ float sh_mq[NP];    // -ln2 / resamp_p (fast path)
    __shared__ float sh_pg[NP];    // raw prob column

    int b    = blockIdx.x >> 2;
    int g    = blockIdx.x & 3;
    int t    = threadIdx.x;
    int w    = t >> 5;
    int lane = t & 31;

    if (t < NP) {
        float pr = prob[t * NB + b];
        float r  = 0.5f * expf(pr) + CQ;
        sh_pg[t] = pr;
        sh_lt[t] = logf(r);
        sh_mq[t] = -0.693147180559945f / r;
    }
    __syncthreads();

    float mq0 = sh_mq[lane];
    float mq1 = sh_mq[lane + 32];
    float mq2 = sh_mq[lane + 64];
    float mq3 = sh_mq[lane + 96];

    const float4* pf4 = (const float4*)particles;

    #pragma unroll 1
    for (int k = 0; k < 2; k++) {
        int s0 = g * 32 + w * 4 + 2 * k;               // draws s0, s0+1
        unsigned base0 = (unsigned)s0 * 65536u + (unsigned)b * 128u;
        unsigned base1 = base0 + 65536u;

        // per-lane packed (key|p) min and second-min, per draw
        unsigned mA = 0xFFFFFFFFu, sA = 0xFFFFFFFFu;
        unsigned mB = 0xFFFFFFFFu, sB = 0xFFFFFFFFu;
        #pragma unroll
        for (int j = 0; j < 4; j++) {
            int p = lane + 32 * j;
            float mqp = (j == 0) ? mq0 : (j == 1) ? mq1 : (j == 2) ? mq2 : mq3;
            unsigned pkA = fast_key_packed(tf_bits_bal(base0 + (unsigned)p, one), mqp, p);
            unsigned pkB = fast_key_packed(tf_bits_bal(base1 + (unsigned)p, one), mqp, p);
            unsigned nA = umin(mA, pkA); sA = umin(sA, umax(mA, pkA)); mA = nA;
            unsigned nB = umin(mB, pkB); sB = umin(sB, umax(mB, pkB)); mB = nB;
        }
        unsigned bestA = __reduce_min_sync(0xffffffffu, mA);
        unsigned bestB = __reduce_min_sync(0xffffffffu, mB);
        int bp0 = (int)(bestA & 127u);
        int bp1 = (int)(bestB & 127u);

        // band check: count candidates with key < best*(1+BAND); >=2 -> fallback
        unsigned thrA = __float_as_uint(__uint_as_float(bestA & 0xFFFFFF80u) * (1.0f + BAND));
        unsigned thrB = __float_as_uint(__uint_as_float(bestB & 0xFFFFFF80u) * (1.0f + BAND));
        unsigned c = (unsigned)(mA < thrA) + (unsigned)(sA < thrA)
                   + (((unsigned)(mB < thrB) + (unsigned)(sB < thrB)) << 16);
        unsigned cnt = __reduce_add_sync(0xffffffffu, c);
        bool fb0 = (cnt & 0xffffu) >= 2u;
        bool fb1 = (cnt >> 16) >= 2u;

        if (fb0 | fb1) {
            // exact round-7 decision (bit-exact reference path)
            float pbA = -CUDART_INF_F, pbB = -CUDART_INF_F;
            int qA = 0, qB = 0;
            #pragma unroll
            for (int j = 0; j < 4; j++) {
                int p = lane + 32 * j;
                float ltp = sh_lt[p];
                float uA = uniform_from_bits(tf_bits(base0 + (unsigned)p));
                float uB = uniform_from_bits(tf_bits(base1 + (unsigned)p));
                float vA = gumbel_precise(uA) + ltp;
                float vB = gumbel_precise(uB) + ltp;
                if (vA > pbA) { pbA = vA; qA = p; }
                if (vB > pbB) { pbB = vB; qB = p; }
            }
            #pragma unroll
            for (int off = 16; off > 0; off >>= 1) {
                float ovA = __shfl_xor_sync(0xffffffffu, pbA, off);
                int   oqA = __shfl_xor_sync(0xffffffffu, qA, off);
                float ovB = __shfl_xor_sync(0xffffffffu, pbB, off);
                int   oqB = __shfl_xor_sync(0xffffffffu, qB, off);
                if (ovA > pbA || (ovA == pbA && oqA < qA)) { pbA = ovA; qA = oqA; }
                if (ovB > pbB || (ovB == pbB && oqB < qB)) { pbB = ovB; qB = oqB; }
            }
            if (fb0) bp0 = qA;
            if (fb1) bp1 = qB;
        }

        // gather row A (4 loads in flight, then stores) — peak 16 live regs
        {
            const float4* srcA = pf4 + ((size_t)bp0 * NB + b) * (NH / 4);
            float4* dstA = (float4*)out_particles + ((size_t)s0 * NB + b) * (NH / 4);
            float4 a0 = srcA[lane];
            float4 a1 = srcA[lane + 32];
            float4 a2 = srcA[lane + 64];
            float4 a3 = srcA[lane + 96];
            dstA[lane]      = a0;
            dstA[lane + 32] = a1;
            dstA[lane + 64] = a2;
            dstA[lane + 96] = a3;
        }
        // gather row B
        {
            const float4* srcB = pf4 + ((size_t)bp1 * NB + b) * (NH / 4);
            float4* dstB = (float4*)out_particles + ((size_t)(s0 + 1) * NB + b) * (NH / 4);
            float4 c0 = srcB[lane];
            float4 c1 = srcB[lane + 32];
            float4 c2 = srcB[lane + 64];
            float4 c3 = srcB[lane + 96];
            dstB[lane]      = c0;
            dstB[lane + 32] = c1;
            dstB[lane + 64] = c2;
            dstB[lane + 96] = c3;
        }

        if (lane == 0) {
            // exact reference composition: w=exp(p); w2=w/(a*w+c); lw=log(w2)
            float pg0 = sh_pg[bp0];
            float pg1 = sh_pg[bp1];
            float wq0 = expf(pg0);
            float wq1 = expf(pg1);
            d_lw[b * NP + s0]     = logf(wq0 / (0.5f * wq0 + CQ));
            d_lw[b * NP + s0 + 1] = logf(wq1 / (0.5f * wq1 + CQ));
        }
    }

    // --- warp-autonomous tail: 32nd arriving warp finishes column b ---
    unsigned lastf = 0;
    if (lane == 0) {
        __threadfence();               // release: this thread's d_lw stores visible
        int old = atomicAdd(&d_cnt[b], 1);
        lastf = (old == 31);
        if (lastf) d_cnt[b] = 0;       // self-reset -> deterministic graph replays
    }
    lastf = __shfl_sync(0xffffffffu, lastf, 0);
    if (lastf) {
        __threadfence();               // acquire side
        const float* lwp = d_lw + b * NP;
        float lw[4];
        float m = -CUDART_INF_F;
        #pragma unroll
        for (int kk = 0; kk < 4; kk++) {
            lw[kk] = lwp[lane + 32 * kk];
            m = fmaxf(m, lw[kk]);
        }
        #pragma unroll
        for (int off = 16; off > 0; off >>= 1)
            m = fmaxf(m, __shfl_xor_sync(0xffffffffu, m, off));
        float e = 0.0f;
        #pragma unroll
        for (int kk = 0; kk < 4; kk++) e += expf(lw[kk] - m);
        #pragma unroll
        for (int off = 16; off > 0; off >>= 1)
            e += __shfl_xor_sync(0xffffffffu, e, off);
        float lse = m + logf(e);
        #pragma unroll
        for (int kk = 0; kk < 4; kk++)
            out_prob[(lane + 32 * kk) * NB + b] = lw[kk] - lse;
    }
}

extern "C" void kernel_launch(void* const* d_in, const int* in_sizes, int n_in,
                              void* d_out, int out_size) {
    const float* particles = (const float*)d_in[0];   // [P*B, H]
    const float* prob      = (const float*)d_in[1];   // [P*B, 1]
    float* out = (float*)d_out;
    float* out_particles = out;                 // [P*B*H]
    float* out_prob = out + (size_t)PB * NH;    // [P*B]

    sample_gather_kernel<<<NB * 4, 256>>>(particles, prob, out_particles, out_prob, 1u);
}

// round 15
// speedup vs baseline: 1.1047x; 1.1047x over previous
#include <cuda_runtime.h>
#include <math_constants.h>

#define NP 128           // particles
#define NB 512           // batch
#define NH 512           // hidden
#define PB (NP*NB)       // 65536
#define CQ 0.00390625f   // (1-alpha)/P = 0.5/128
#define BAND 0.004f      // near-tie fallback band (rel); fast-key err <= ~6e-5

// threefry key from jax.random.key(42): (k0=0, k1=42)
#define KS0 0u
#define KS1 42u
#define KS2 (KS0 ^ KS1 ^ 0x1BD11BDAu)

// 64 warps contribute to each column's d_lw (8 blocks/column x 8 warps)
#define WARPS_PER_COL 64

__device__ float d_lw[PB];    // d_lw[b*128 + s]
__device__ int   d_cnt[NB];   // warp-arrival counters (zero-init; self-reset)

// opaque multiply-by-one -> IMAD on the fma pipe, bit-exact
__device__ __forceinline__ unsigned imad1(unsigned a, unsigned one, unsigned c) {
    unsigned d;
    asm("mad.lo.u32 %0, %1, %2, %3;" : "=r"(d) : "r"(a), "r"(one), "r"(c));
    return d;
}

// fast-path threefry round: add on fma pipe, rot+xor on alu pipe
#define TFR(r) { x0 = imad1(x0, one, x1); x1 = __funnelshift_l(x1, x1, (r)); x1 ^= x0; }
// exact fallback-path round (original form; same bits either way)
#define TFROUND(r) { x0 += x1; x1 = __funnelshift_l(x1, x1, (r)); x1 ^= x0; }

// jax partitionable threefry, pipe-balanced (bit-identical)
__device__ __forceinline__ unsigned tf_bits_bal(unsigned i, unsigned one) {
    unsigned x0 = KS0;
    unsigned x1 = i + KS1;
    TFR(13) TFR(15) TFR(26) TFR(6)
    x0 = imad1(x0, one, KS1); x1 = imad1(x1, one, KS2 + 1u);
    TFR(17) TFR(29) TFR(16) TFR(24)
    x0 = imad1(x0, one, KS2); x1 = imad1(x1, one, KS0 + 2u);
    TFR(13) TFR(15) TFR(26) TFR(6)
    x0 = imad1(x0, one, KS0); x1 = imad1(x1, one, KS1 + 3u);
    TFR(17) TFR(29) TFR(16) TFR(24)
    x0 = imad1(x0, one, KS1); x1 = imad1(x1, one, KS2 + 4u);
    TFR(13) TFR(15) TFR(26) TFR(6)
    x0 = imad1(x0, one, KS2); x1 = imad1(x1, one, KS0 + 5u);
    return x0 ^ x1;
}

// exact-path threefry (identical bits; used in fallback)
__device__ __forceinline__ unsigned tf_bits(unsigned i) {
    unsigned x0 = KS0;
    unsigned x1 = i + KS1;
    TFROUND(13) TFROUND(15) TFROUND(26) TFROUND(6)
    x0 += KS1; x1 += KS2 + 1u;
    TFROUND(17) TFROUND(29) TFROUND(16) TFROUND(24)
    x0 += KS2; x1 += KS0 + 2u;
    TFROUND(13) TFROUND(15) TFROUND(26) TFROUND(6)
    x0 += KS0; x1 += KS1 + 3u;
    TFROUND(17) TFROUND(29) TFROUND(16) TFROUND(24)
    x0 += KS1; x1 += KS2 + 4u;
    TFROUND(13) TFROUND(15) TFROUND(26) TFROUND(6)
    x0 += KS2; x1 += KS0 + 5u;
    return x0 ^ x1;
}

__device__ __forceinline__ float uniform_from_bits(unsigned bits) {  // fallback path
    unsigned fb = (bits >> 9) | 0x3f800000u;
    float f = __uint_as_float(fb) - 1.0f;
    return fmaxf(f, 1.17549435082228751e-38f);
}

__device__ __forceinline__ float gumbel_precise(float u) {           // fallback path
    return -logf(-logf(u));
}

// fast path: u via IMAD.HI (fma pipe), key = lg2(u)*mq (positive, argmin).
// near-1 branchless poly fix (err <= ~5e-6 rel, band covers).
__device__ __forceinline__ unsigned fast_key_packed(unsigned bits, float mq, int p) {
    unsigned fb = __umulhi(bits, 0x800000u) + 0x3f800000u;  // == (bits>>9)|0x3f800000
    float u = __uint_as_float(fb) - 1.0f;                   // u==0 -> key=+inf (never wins)
    float lgm = __log2f(u);
    float x = u - 1.0f;
    float lgp = x * fmaf(x, -0.7213475204444817f, 1.4426950408889634f);
    float lg = (u > 0.996f) ? lgp : lgm;
    float key = lg * mq;
    return (__float_as_uint(key) & 0xFFFFFF80u) | (unsigned)p;
}

// Single kernel: block (b, g) owns draws s = g*16 .. g*16+15 of column b.
// One draw-pair per warp (round-12 shape). Warps retire independently; the
// 64th arriving warp of a column computes that column's logsumexp.
__global__ __launch_bounds__(256, 7) void sample_gather_kernel(
        const float* __restrict__ particles,
        const float* __restrict__ prob,
        float* __restrict__ out_particles,
        float* __restrict__ out_prob,
        unsigned one) {
    __shared__ float sh_lt[NP];    // log(resamp_p)   (exact path)
    __shared__ float sh_mq[NP];    // -ln2 / resamp_p (fast path)
    __shared__ float sh_pg[NP];    // raw prob column

    int b    = blockIdx.x >> 3;
    int g    = blockIdx.x & 7;
    int t    = threadIdx.x;
    int w    = t >> 5;
    int lane = t & 31;

    if (t < NP) {
        float pr = prob[t * NB + b];
        float r  = 0.5f * expf(pr) + CQ;
        sh_pg[t] = pr;
        sh_lt[t] = logf(r);
        sh_mq[t] = -0.693147180559945f / r;
    }
    __syncthreads();

    float mq0 = sh_mq[lane];
    float mq1 = sh_mq[lane + 32];
    float mq2 = sh_mq[lane + 64];
    float mq3 = sh_mq[lane + 96];

    int s0 = g * 16 + w * 2;                       // draws s0, s0+1
    unsigned base0 = (unsigned)s0 * 65536u + (unsigned)b * 128u;
    unsigned base1 = base0 + 65536u;

    // per-lane packed (key|p) min and second-min, per draw
    unsigned mA = 0xFFFFFFFFu, sA = 0xFFFFFFFFu;
    unsigned mB = 0xFFFFFFFFu, sB = 0xFFFFFFFFu;
    #pragma unroll
    for (int j = 0; j < 4; j++) {
        int p = lane + 32 * j;
        float mqp = (j == 0) ? mq0 : (j == 1) ? mq1 : (j == 2) ? mq2 : mq3;
        unsigned pkA = fast_key_packed(tf_bits_bal(base0 + (unsigned)p, one), mqp, p);
        unsigned pkB = fast_key_packed(tf_bits_bal(base1 + (unsigned)p, one), mqp, p);
        unsigned nA = umin(mA, pkA); sA = umin(sA, umax(mA, pkA)); mA = nA;
        unsigned nB = umin(mB, pkB); sB = umin(sB, umax(mB, pkB)); mB = nB;
    }
    // warp argmin in one instruction; tie -> lower p automatic (p in low bits)
    unsigned bestA = __reduce_min_sync(0xffffffffu, mA);
    unsigned bestB = __reduce_min_sync(0xffffffffu, mB);
    int bp0 = (int)(bestA & 127u);
    int bp1 = (int)(bestB & 127u);

    // band check: count candidates with key < best*(1+BAND); >=2 -> fallback
    unsigned thrA = __float_as_uint(__uint_as_float(bestA & 0xFFFFFF80u) * (1.0f + BAND));
    unsigned thrB = __float_as_uint(__uint_as_float(bestB & 0xFFFFFF80u) * (1.0f + BAND));
    unsigned c = (unsigned)(mA < thrA) + (unsigned)(sA < thrA)
               + (((unsigned)(mB < thrB) + (unsigned)(sB < thrB)) << 16);
    unsigned cnt = __reduce_add_sync(0xffffffffu, c);
    bool fb0 = (cnt & 0xffffu) >= 2u;
    bool fb1 = (cnt >> 16) >= 2u;

    if (fb0 | fb1) {
        // exact round-7 decision (bit-exact reference path)
        float pbA = -CUDART_INF_F, pbB = -CUDART_INF_F;
        int qA = 0, qB = 0;
        #pragma unroll
        for (int j = 0; j < 4; j++) {
            int p = lane + 32 * j;
            float ltp = sh_lt[p];
            float uA = uniform_from_bits(tf_bits(base0 + (unsigned)p));
            float uB = uniform_from_bits(tf_bits(base1 + (unsigned)p));
            float vA = gumbel_precise(uA) + ltp;
            float vB = gumbel_precise(uB) + ltp;
            if (vA > pbA) { pbA = vA; qA = p; }
            if (vB > pbB) { pbB = vB; qB = p; }
        }
        #pragma unroll
        for (int off = 16; off > 0; off >>= 1) {
            float ovA = __shfl_xor_sync(0xffffffffu, pbA, off);
            int   oqA = __shfl_xor_sync(0xffffffffu, qA, off);
            float ovB = __shfl_xor_sync(0xffffffffu, pbB, off);
            int   oqB = __shfl_xor_sync(0xffffffffu, qB, off);
            if (ovA > pbA || (ovA == pbA && oqA < qA)) { pbA = ovA; qA = oqA; }
            if (ovB > pbB || (ovB == pbB && oqB < qB)) { pbB = ovB; qB = oqB; }
        }
        if (fb0) bp0 = qA;
        if (fb1) bp1 = qB;
    }

    // gather row A (4 loads in flight, then stores) — peak 16 live regs
    const float4* pf4 = (const float4*)particles;
    {
        const float4* srcA = pf4 + ((size_t)bp0 * NB + b) * (NH / 4);
        float4* dstA = (float4*)out_particles + ((size_t)s0 * NB + b) * (NH / 4);
        float4 a0 = srcA[lane];
        float4 a1 = srcA[lane + 32];
        float4 a2 = srcA[lane + 64];
        float4 a3 = srcA[lane + 96];
        dstA[lane]      = a0;
        dstA[lane + 32] = a1;
        dstA[lane + 64] = a2;
        dstA[lane + 96] = a3;
    }
    // gather row B
    {
        const float4* srcB = pf4 + ((size_t)bp1 * NB + b) * (NH / 4);
        float4* dstB = (float4*)out_particles + ((size_t)(s0 + 1) * NB + b) * (NH / 4);
        float4 c0 = srcB[lane];
        float4 c1 = srcB[lane + 32];
        float4 c2 = srcB[lane + 64];
        float4 c3 = srcB[lane + 96];
        dstB[lane]      = c0;
        dstB[lane + 32] = c1;
        dstB[lane + 64] = c2;
        dstB[lane + 96] = c3;
    }

    if (lane == 0) {
        // exact reference composition: w=exp(p); w2=w/(a*w+c); lw=log(w2)
        float pg0 = sh_pg[bp0];
        float pg1 = sh_pg[bp1];
        float wq0 = expf(pg0);
        float wq1 = expf(pg1);
        d_lw[b * NP + s0]     = logf(wq0 / (0.5f * wq0 + CQ));
        d_lw[b * NP + s0 + 1] = logf(wq1 / (0.5f * wq1 + CQ));
    }

    // --- warp-autonomous tail: 64th arriving warp finishes column b ---
    unsigned lastf = 0;
    if (lane == 0) {
        __threadfence();               // release: this thread's d_lw stores visible
        int old = atomicAdd(&d_cnt[b], 1);
        lastf = (old == WARPS_PER_COL - 1);
        if (lastf) d_cnt[b] = 0;       // self-reset -> deterministic graph replays
    }
    lastf = __shfl_sync(0xffffffffu, lastf, 0);
    if (lastf) {
        __threadfence();               // acquire side
        const float* lwp = d_lw + b * NP;
        float lw[4];
        float m = -CUDART_INF_F;
        #pragma unroll
        for (int kk = 0; kk < 4; kk++) {
            lw[kk] = lwp[lane + 32 * kk];
            m = fmaxf(m, lw[kk]);
        }
        #pragma unroll
        for (int off = 16; off > 0; off >>= 1)
            m = fmaxf(m, __shfl_xor_sync(0xffffffffu, m, off));
        float e = 0.0f;
        #pragma unroll
        for (int kk = 0; kk < 4; kk++) e += expf(lw[kk] - m);
        #pragma unroll
        for (int off = 16; off > 0; off >>= 1)
            e += __shfl_xor_sync(0xffffffffu, e, off);
        float lse = m + logf(e);
        #pragma unroll
        for (int kk = 0; kk < 4; kk++)
            out_prob[(lane + 32 * kk) * NB + b] = lw[kk] - lse;
    }
}

extern "C" void kernel_launch(void* const* d_in, const int* in_sizes, int n_in,
                              void* d_out, int out_size) {
    const float* particles = (const float*)d_in[0];   // [P*B, H]
    const float* prob      = (const float*)d_in[1];   // [P*B, 1]
    float* out = (float*)d_out;
    float* out_particles = out;                 // [P*B*H]
    float* out_prob = out + (size_t)PB * NH;    // [P*B]

    sample_gather_kernel<<<NB * 8, 256>>>(particles, prob, out_particles, out_prob, 1u);
}

// round 16
// speedup vs baseline: 1.1854x; 1.0730x over previous
#include <cuda_runtime.h>
#include <math_constants.h>

#define NP 128           // particles
#define NB 512           // batch
#define NH 512           // hidden
#define PB (NP*NB)       // 65536
#define CQ 0.00390625f   // (1-alpha)/P = 0.5/128
#define BAND 0.004f      // near-tie fallback band (rel); fast-key err <= ~6e-5

// threefry key from jax.random.key(42): (k0=0, k1=42)
#define KS0 0u
#define KS1 42u
#define KS2 (KS0 ^ KS1 ^ 0x1BD11BDAu)

__device__ float d_lw[PB];    // d_lw[b*128 + s]
__device__ int   d_cnt[NB];   // block-arrival counters (zero-init; self-reset)

// opaque multiply-by-one -> IMAD on the fma pipe, bit-exact
__device__ __forceinline__ unsigned imad1(unsigned a, unsigned one, unsigned c) {
    unsigned d;
    asm("mad.lo.u32 %0, %1, %2, %3;" : "=r"(d) : "r"(a), "r"(one), "r"(c));
    return d;
}

// fast-path threefry round: add on fma pipe, rot+xor on alu pipe
#define TFR(r) { x0 = imad1(x0, one, x1); x1 = __funnelshift_l(x1, x1, (r)); x1 ^= x0; }
// exact fallback-path round (original form; same bits either way)
#define TFROUND(r) { x0 += x1; x1 = __funnelshift_l(x1, x1, (r)); x1 ^= x0; }

// jax partitionable threefry, pipe-balanced (bit-identical)
__device__ __forceinline__ unsigned tf_bits_bal(unsigned i, unsigned one) {
    unsigned x0 = KS0;
    unsigned x1 = i + KS1;
    TFR(13) TFR(15) TFR(26) TFR(6)
    x0 = imad1(x0, one, KS1); x1 = imad1(x1, one, KS2 + 1u);
    TFR(17) TFR(29) TFR(16) TFR(24)
    x0 = imad1(x0, one, KS2); x1 = imad1(x1, one, KS0 + 2u);
    TFR(13) TFR(15) TFR(26) TFR(6)
    x0 = imad1(x0, one, KS0); x1 = imad1(x1, one, KS1 + 3u);
    TFR(17) TFR(29) TFR(16) TFR(24)
    x0 = imad1(x0, one, KS1); x1 = imad1(x1, one, KS2 + 4u);
    TFR(13) TFR(15) TFR(26) TFR(6)
    x0 = imad1(x0, one, KS2); x1 = imad1(x1, one, KS0 + 5u);
    return x0 ^ x1;
}

// exact-path threefry (identical bits; used in fallback)
__device__ __forceinline__ unsigned tf_bits(unsigned i) {
    unsigned x0 = KS0;
    unsigned x1 = i + KS1;
    TFROUND(13) TFROUND(15) TFROUND(26) TFROUND(6)
    x0 += KS1; x1 += KS2 + 1u;
    TFROUND(17) TFROUND(29) TFROUND(16) TFROUND(24)
    x0 += KS2; x1 += KS0 + 2u;
    TFROUND(13) TFROUND(15) TFROUND(26) TFROUND(6)
    x0 += KS0; x1 += KS1 + 3u;
    TFROUND(17) TFROUND(29) TFROUND(16) TFROUND(24)
    x0 += KS1; x1 += KS2 + 4u;
    TFROUND(13) TFROUND(15) TFROUND(26) TFROUND(6)
    x0 += KS2; x1 += KS0 + 5u;
    return x0 ^ x1;
}

__device__ __forceinline__ float uniform_from_bits(unsigned bits) {  // fallback path
    unsigned fb = (bits >> 9) | 0x3f800000u;
    float f = __uint_as_float(fb) - 1.0f;
    return fmaxf(f, 1.17549435082228751e-38f);
}

__device__ __forceinline__ float gumbel_precise(float u) {           // fallback path
    return -logf(-logf(u));
}

// fast path: u via IMAD.HI (fma pipe), key = lg2(u)*mq (positive, argmin).
// near-1 branchless poly fix (err <= ~5e-6 rel, band covers).
__device__ __forceinline__ unsigned fast_key_packed(unsigned bits, float mq, int p) {
    unsigned fb = __umulhi(bits, 0x800000u) + 0x3f800000u;  // == (bits>>9)|0x3f800000
    float u = __uint_as_float(fb) - 1.0f;                   // u==0 -> key=+inf (never wins)
    float lgm = __log2f(u);
    float x = u - 1.0f;
    float lgp = x * fmaf(x, -0.7213475204444817f, 1.4426950408889634f);
    float lg = (u > 0.996f) ? lgp : lgm;
    float key = lg * mq;
    return (__float_as_uint(key) & 0xFFFFFF80u) | (unsigned)p;
}

// Single kernel (round-12 shape): block (b, g) owns draws s = g*16..g*16+15 of
// column b; one draw-pair per warp. Output stores are streaming (__stwt) so
// the 128MB write stream does not evict the particle source from L2.
__global__ __launch_bounds__(256, 7) void sample_gather_kernel(
        const float* __restrict__ particles,
        const float* __restrict__ prob,
        float* __restrict__ out_particles,
        float* __restrict__ out_prob,
        unsigned one) {
    __shared__ float sh_lt[NP];    // log(resamp_p)   (exact path)
    __shared__ float sh_mq[NP];    // -ln2 / resamp_p (fast path)
    __shared__ float sh_pg[NP];    // raw prob column
    __shared__ int   sh_last;

    int b    = blockIdx.x >> 3;
    int g    = blockIdx.x & 7;
    int t    = threadIdx.x;
    int w    = t >> 5;
    int lane = t & 31;

    if (t < NP) {
        float pr = prob[t * NB + b];
        float r  = 0.5f * expf(pr) + CQ;
        sh_pg[t] = pr;
        sh_lt[t] = logf(r);
        sh_mq[t] = -0.693147180559945f / r;
    }
    __syncthreads();

    float mq0 = sh_mq[lane];
    float mq1 = sh_mq[lane + 32];
    float mq2 = sh_mq[lane + 64];
    float mq3 = sh_mq[lane + 96];

    int s0 = g * 16 + w * 2;                       // draws s0, s0+1
    unsigned base0 = (unsigned)s0 * 65536u + (unsigned)b * 128u;
    unsigned base1 = base0 + 65536u;

    // per-lane packed (key|p) min and second-min, per draw
    unsigned mA = 0xFFFFFFFFu, sA = 0xFFFFFFFFu;
    unsigned mB = 0xFFFFFFFFu, sB = 0xFFFFFFFFu;
    #pragma unroll
    for (int j = 0; j < 4; j++) {
        int p = lane + 32 * j;
        float mqp = (j == 0) ? mq0 : (j == 1) ? mq1 : (j == 2) ? mq2 : mq3;
        unsigned pkA = fast_key_packed(tf_bits_bal(base0 + (unsigned)p, one), mqp, p);
        unsigned pkB = fast_key_packed(tf_bits_bal(base1 + (unsigned)p, one), mqp, p);
        unsigned nA = umin(mA, pkA); sA = umin(sA, umax(mA, pkA)); mA = nA;
        unsigned nB = umin(mB, pkB); sB = umin(sB, umax(mB, pkB)); mB = nB;
    }
    // warp argmin in one instruction; tie -> lower p automatic (p in low bits)
    unsigned bestA = __reduce_min_sync(0xffffffffu, mA);
    unsigned bestB = __reduce_min_sync(0xffffffffu, mB);
    int bp0 = (int)(bestA & 127u);
    int bp1 = (int)(bestB & 127u);

    // band check: count candidates with key < best*(1+BAND); >=2 -> fallback
    unsigned thrA = __float_as_uint(__uint_as_float(bestA & 0xFFFFFF80u) * (1.0f + BAND));
    unsigned thrB = __float_as_uint(__uint_as_float(bestB & 0xFFFFFF80u) * (1.0f + BAND));
    unsigned c = (unsigned)(mA < thrA) + (unsigned)(sA < thrA)
               + (((unsigned)(mB < thrB) + (unsigned)(sB < thrB)) << 16);
    unsigned cnt = __reduce_add_sync(0xffffffffu, c);
    bool fb0 = (cnt & 0xffffu) >= 2u;
    bool fb1 = (cnt >> 16) >= 2u;

    if (fb0 | fb1) {
        // exact round-7 decision (bit-exact reference path)
        float pbA = -CUDART_INF_F, pbB = -CUDART_INF_F;
        int qA = 0, qB = 0;
        #pragma unroll
        for (int j = 0; j < 4; j++) {
            int p = lane + 32 * j;
            float ltp = sh_lt[p];
            float uA = uniform_from_bits(tf_bits(base0 + (unsigned)p));
            float uB = uniform_from_bits(tf_bits(base1 + (unsigned)p));
            float vA = gumbel_precise(uA) + ltp;
            float vB = gumbel_precise(uB) + ltp;
            if (vA > pbA) { pbA = vA; qA = p; }
            if (vB > pbB) { pbB = vB; qB = p; }
        }
        #pragma unroll
        for (int off = 16; off > 0; off >>= 1) {
            float ovA = __shfl_xor_sync(0xffffffffu, pbA, off);
            int   oqA = __shfl_xor_sync(0xffffffffu, qA, off);
            float ovB = __shfl_xor_sync(0xffffffffu, pbB, off);
            int   oqB = __shfl_xor_sync(0xffffffffu, qB, off);
            if (ovA > pbA || (ovA == pbA && oqA < qA)) { pbA = ovA; qA = oqA; }
            if (ovB > pbB || (ovB == pbB && oqB < qB)) { pbB = ovB; qB = oqB; }
        }
        if (fb0) bp0 = qA;
        if (fb1) bp1 = qB;
    }

    // gather row A (4 loads in flight, then streaming stores) — peak 16 live regs
    const float4* pf4 = (const float4*)particles;
    {
        const float4* srcA = pf4 + ((size_t)bp0 * NB + b) * (NH / 4);
        float4* dstA = (float4*)out_particles + ((size_t)s0 * NB + b) * (NH / 4);
        float4 a0 = srcA[lane];
        float4 a1 = srcA[lane + 32];
        float4 a2 = srcA[lane + 64];
        float4 a3 = srcA[lane + 96];
        __stwt(dstA + lane,      a0);
        __stwt(dstA + lane + 32, a1);
        __stwt(dstA + lane + 64, a2);
        __stwt(dstA + lane + 96, a3);
    }
    // gather row B
    {
        const float4* srcB = pf4 + ((size_t)bp1 * NB + b) * (NH / 4);
        float4* dstB = (float4*)out_particles + ((size_t)(s0 + 1) * NB + b) * (NH / 4);
        float4 c0 = srcB[lane];
        float4 c1 = srcB[lane + 32];
        float4 c2 = srcB[lane + 64];
        float4 c3 = srcB[lane + 96];
        __stwt(dstB + lane,      c0);
        __stwt(dstB + lane + 32, c1);
        __stwt(dstB + lane + 64, c2);
        __stwt(dstB + lane + 96, c3);
    }

    if (lane == 0) {
        // exact reference composition: w=exp(p); w2=w/(a*w+c); lw=log(w2)
        float pg0 = sh_pg[bp0];
        float pg1 = sh_pg[bp1];
        float wq0 = expf(pg0);
        float wq1 = expf(pg1);
        d_lw[b * NP + s0]     = logf(wq0 / (0.5f * wq0 + CQ));
        d_lw[b * NP + s0 + 1] = logf(wq1 / (0.5f * wq1 + CQ));
    }

    // --- per-column tail: 8th arriving block finishes column b (round-12 form) ---
    __syncthreads();
    if (t == 0) {
        __threadfence();               // release: block's lw stores visible
        int old = atomicAdd(&d_cnt[b], 1);
        sh_last = (old == 7);
        if (old == 7) d_cnt[b] = 0;    // self-reset -> deterministic graph replays
    }
    __syncthreads();
    if (sh_last && w == 0) {
        __threadfence();               // acquire side
        const float* lwp = d_lw + b * NP;
        float lw[4];
        float m = -CUDART_INF_F;
        #pragma unroll
        for (int kk = 0; kk < 4; kk++) {
            lw[kk] = lwp[lane + 32 * kk];
            m = fmaxf(m, lw[kk]);
        }
        #pragma unroll
        for (int off = 16; off > 0; off >>= 1)
            m = fmaxf(m, __shfl_xor_sync(0xffffffffu, m, off));
        float e = 0.0f;
        #pragma unroll
        for (int kk = 0; kk < 4; kk++) e += expf(lw[kk] - m);
        #pragma unroll
        for (int off = 16; off > 0; off >>= 1)
            e += __shfl_xor_sync(0xffffffffu, e, off);
        float lse = m + logf(e);
        #pragma unroll
        for (int kk = 0; kk < 4; kk++)
            out_prob[(lane + 32 * kk) * NB + b] = lw[kk] - lse;
    }
}

extern "C" void kernel_launch(void* const* d_in, const int* in_sizes, int n_in,
                              void* d_out, int out_size) {
    const float* particles = (const float*)d_in[0];   // [P*B, H]
    const float* prob      = (const float*)d_in[1];   // [P*B, 1]
    float* out = (float*)d_out;
    float* out_particles = out;                 // [P*B*H]
    float* out_prob = out + (size_t)PB * NH;    // [P*B]

    sample_gather_kernel<<<NB * 8, 256>>>(particles, prob, out_particles, out_prob, 1u);
}